// round 8
// baseline (speedup 1.0000x reference)
#include <cuda_runtime.h>
#include <cuda_bf16.h>
#include <mma.h>
#include <math.h>
#include <stdint.h>

using namespace nvcuda;

// ---------------- static scratch (no allocation allowed) ----------------
#define N_MAX 150016
#define E_MAX 900032

__device__ float g_y[(size_t)N_MAX * 256];   // GEMM output (pre-BN)
__device__ float g_z[(size_t)N_MAX * 96];    // aggregated input features
__device__ float g_x[(size_t)N_MAX * 128];   // fc0 output (pre-relu; relu in segmax)
__device__ int   g_deg[N_MAX];
__device__ int   g_cursor[N_MAX];
__device__ int   g_rowptr[N_MAX + 1];
__device__ int   g_csr_src[E_MAX];
__device__ float g_csr_w[E_MAX];
__device__ float g_dinv[N_MAX];
__device__ float g_cs[N_MAX];
__device__ int   g_blocksum[256];
__device__ int   g_blockoff[257];
__device__ float g_sum[256];
__device__ float g_sq[256];
__device__ float g_scale[256];
__device__ float g_shift[256];
__device__ float g_pool[64 * 128];
__device__ int   g_starts[65];
__device__ __nv_bfloat16 g_wt_hi[288 * 256];  // split weights+bias row, [Kpad][NTpad]
__device__ __nv_bfloat16 g_wt_lo[288 * 256];

// ---------------- prep kernels ----------------
__global__ void k_zero(int n) {
    int i = blockIdx.x * blockDim.x + threadIdx.x;
    if (i < n) { g_deg[i] = 0; g_cursor[i] = 0; }
    if (i < 256) { g_sum[i] = 0.f; g_sq[i] = 0.f; }
}

__global__ void k_hist(const int* __restrict__ dst, int e) {
    int i = blockIdx.x * blockDim.x + threadIdx.x;
    if (i < e) atomicAdd(&g_deg[dst[i]], 1);
}

__global__ void k_scan1(int n) {
    __shared__ int sh[1024];
    int t = threadIdx.x;
    int idx = blockIdx.x * 1024 + t;
    int v = (idx < n) ? g_deg[idx] : 0;
    sh[t] = v;
    __syncthreads();
    for (int off = 1; off < 1024; off <<= 1) {
        int add = (t >= off) ? sh[t - off] : 0;
        __syncthreads();
        sh[t] += add;
        __syncthreads();
    }
    if (idx < n) {
        g_rowptr[idx] = sh[t] - v;
        float d = (float)(v + 1);
        float r = rsqrtf(d);
        g_dinv[idx] = r;
        g_cs[idx] = r * r;
    }
    if (t == 1023) g_blocksum[blockIdx.x] = sh[t];
}

__global__ void k_scan2(int nb, int n) {
    __shared__ int sh[256];
    int t = threadIdx.x;
    int v = (t < nb) ? g_blocksum[t] : 0;
    sh[t] = v;
    __syncthreads();
    for (int off = 1; off < 256; off <<= 1) {
        int add = (t >= off) ? sh[t - off] : 0;
        __syncthreads();
        sh[t] += add;
        __syncthreads();
    }
    int total = sh[255];
    if (t < nb) g_blockoff[t] = sh[t] - v;
    if (t == nb) g_blockoff[nb] = total;
    if (t == (n >> 10)) g_rowptr[n] = total - (sh[t] - v);
}

__device__ __forceinline__ int rp(int i) {
    return g_rowptr[i] + g_blockoff[i >> 10];
}

__global__ void k_place(const int* __restrict__ src, const int* __restrict__ dst, int e) {
    int i = blockIdx.x * blockDim.x + threadIdx.x;
    if (i < e) {
        int d = dst[i], s = src[i];
        int p = rp(d) + atomicAdd(&g_cursor[d], 1);
        g_csr_src[p] = s;
        g_csr_w[p] = g_dinv[s] * g_dinv[d];
    }
}

// ---------------- aggregation (fused BN+ReLU on input) ----------------
template<int MODE>
__global__ void k_agg(const float* __restrict__ xext, int n, int din) {
    const float* __restrict__ x = (MODE == 0) ? xext : g_y;
    int gt = blockIdx.x * blockDim.x + threadIdx.x;
    int node = gt >> 5;
    int lane = gt & 31;
    if (node >= n) return;
    int c0 = lane, c1 = lane + 32, c2 = lane + 64;
    bool v0 = c0 < din, v1 = c1 < din, v2 = c2 < din;
    float s0 = 1.f, h0 = 0.f, s1 = 1.f, h1 = 0.f, s2 = 1.f, h2 = 0.f;
    if (MODE) {
        if (v0) { s0 = g_scale[c0]; h0 = g_shift[c0]; }
        if (v1) { s1 = g_scale[c1]; h1 = g_shift[c1]; }
        if (v2) { s2 = g_scale[c2]; h2 = g_shift[c2]; }
    }
    int beg = rp(node), end = rp(node + 1);
    float a0 = 0.f, a1 = 0.f, a2 = 0.f;
    for (int p = beg; p < end; p++) {
        int s = g_csr_src[p];
        float w = g_csr_w[p];
        const float* xs = x + (size_t)s * din;
        if (v0) { float v = xs[c0]; if (MODE) v = fmaxf(fmaf(v, s0, h0), 0.f); a0 = fmaf(v, w, a0); }
        if (v1) { float v = xs[c1]; if (MODE) v = fmaxf(fmaf(v, s1, h1), 0.f); a1 = fmaf(v, w, a1); }
        if (v2) { float v = xs[c2]; if (MODE) v = fmaxf(fmaf(v, s2, h2), 0.f); a2 = fmaf(v, w, a2); }
    }
    float cw = g_cs[node];
    const float* xi = x + (size_t)node * din;
    float* zi = g_z + (size_t)node * din;
    if (v0) { float v = xi[c0]; if (MODE) v = fmaxf(fmaf(v, s0, h0), 0.f); zi[c0] = fmaf(v, cw, a0); }
    if (v1) { float v = xi[c1]; if (MODE) v = fmaxf(fmaf(v, s1, h1), 0.f); zi[c1] = fmaf(v, cw, a1); }
    if (v2) { float v = xi[c2]; if (MODE) v = fmaxf(fmaf(v, s2, h2), 0.f); zi[c2] = fmaf(v, cw, a2); }
}

// ---------------- small GEMM (K<=16, NC<=32): thread per row, fused stats ----
template<int K, int NC>
__global__ __launch_bounds__(256) void k_gemm_s(
    const float* __restrict__ Bm, const float* __restrict__ bias, int M)
{
    __shared__ float Ws[K * NC];
    __shared__ float bs[NC];
    int tid = threadIdx.x;
    for (int i = tid; i < K * NC; i += 256) Ws[i] = Bm[i];
    if (tid < NC) bs[tid] = bias[tid];
    __syncthreads();

    int r = blockIdx.x * 256 + tid;
    bool valid = r < M;
    float a[K];
    #pragma unroll
    for (int k = 0; k < K; k++) a[k] = valid ? g_z[(size_t)r * K + k] : 0.f;
    float acc[NC];
    #pragma unroll
    for (int c = 0; c < NC; c++) acc[c] = valid ? bs[c] : 0.f;
    #pragma unroll
    for (int k = 0; k < K; k++)
        #pragma unroll
        for (int c = 0; c < NC; c++) acc[c] = fmaf(a[k], Ws[k * NC + c], acc[c]);

    if (valid) {
        float4* dst = (float4*)(g_y + (size_t)r * NC);
        #pragma unroll
        for (int c = 0; c < NC; c += 4)
            dst[c >> 2] = make_float4(acc[c], acc[c + 1], acc[c + 2], acc[c + 3]);
    }
    float q[NC];
    #pragma unroll
    for (int c = 0; c < NC; c++) q[c] = acc[c] * acc[c];
    #pragma unroll
    for (int off = 16; off; off >>= 1) {
        #pragma unroll
        for (int c = 0; c < NC; c++) {
            acc[c] += __shfl_down_sync(0xffffffffu, acc[c], off);
            q[c]   += __shfl_down_sync(0xffffffffu, q[c], off);
        }
    }
    if ((tid & 31) == 0) {
        #pragma unroll
        for (int c = 0; c < NC; c++) {
            atomicAdd(&g_sum[c], acc[c]);
            atomicAdd(&g_sq[c], q[c]);
        }
    }
}

// ---------------- weight split: W[K][N] fp32 + bias -> [Kpad][NTpad] bf16 ----
// Row K holds the bias (paired with the ones-column appended to A).
__global__ void k_wsplit(const float* __restrict__ W, const float* __restrict__ bias,
                         int K, int N, int NTpad, int Kpad) {
    int i = blockIdx.x * blockDim.x + threadIdx.x;
    if (i >= Kpad * NTpad) return;
    int k = i / NTpad, nn = i % NTpad;
    float v = 0.f;
    if (nn < N) {
        if (k < K) v = W[(size_t)k * N + nn];
        else if (k == K) v = bias[nn];
    }
    __nv_bfloat16 h = __float2bfloat16(v);
    __nv_bfloat16 l = __float2bfloat16(v - __bfloat162float(h));
    g_wt_hi[i] = h;
    g_wt_lo[i] = l;
}

// ---------------- WMMA bf16x3 GEMM: 128x64 block, 8 warps, K in 32-chunks ----
// FC0==0: g_y = g_z @ W  (bias folded via ones-column).
// FC0==1: g_x = relu(bn(g_y)) @ W  (relu deferred to segmax).
#define LDA 40
#define LDB 72
template<int FC0>
__global__ __launch_bounds__(256) void k_wmma(int M, int K, int Nc, int Kpad, int NTpad)
{
    __shared__ __align__(16) char smbuf[32768];
    __nv_bfloat16* Ah = (__nv_bfloat16*)smbuf;                  // 128 x LDA
    __nv_bfloat16* Al = (__nv_bfloat16*)(smbuf + 10240);
    __nv_bfloat16* Bh = (__nv_bfloat16*)(smbuf + 20480);        // 32 x LDB
    __nv_bfloat16* Bl = (__nv_bfloat16*)(smbuf + 25088);
    float* ob = (float*)smbuf;                                  // 128 x 64 staging

    const float* __restrict__ A = FC0 ? g_y : g_z;
    float* __restrict__ C = FC0 ? g_x : g_y;

    int tid = threadIdx.x;
    int wid = tid >> 5;
    int warp_m = wid & 3;        // 0..3
    int warp_n = wid >> 2;       // 0..1
    int row0 = blockIdx.y * 128;
    int col0 = blockIdx.x * 64;

    wmma::fragment<wmma::accumulator, 16, 16, 16, float> acc[2][2];
    #pragma unroll
    for (int mi = 0; mi < 2; mi++)
        #pragma unroll
        for (int ni = 0; ni < 2; ni++) wmma::fill_fragment(acc[mi][ni], 0.f);

    for (int k0 = 0; k0 < Kpad; k0 += 32) {
        // A chunk: 128 rows x 32 k, split to hi/lo (ones-column at gk==K)
        for (int i = tid; i < 128 * 32; i += 256) {
            int r = i >> 5, kk = i & 31;
            int gk = k0 + kk;
            int row = row0 + r;
            float v = 0.f;
            if (row < M) {
                if (gk < K) {
                    v = A[(size_t)row * K + gk];
                    if (FC0) v = fmaxf(fmaf(v, g_scale[gk], g_shift[gk]), 0.f);
                } else if (gk == K) v = 1.f;
            }
            __nv_bfloat16 h = __float2bfloat16(v);
            __nv_bfloat16 l = __float2bfloat16(v - __bfloat162float(h));
            Ah[r * LDA + kk] = h;
            Al[r * LDA + kk] = l;
        }
        // B chunk: 32 k x 64 n from pre-split weights [Kpad][NTpad]
        for (int i = tid; i < 32 * 64; i += 256) {
            int kk = i >> 6, nn = i & 63;
            int widx = (k0 + kk) * NTpad + col0 + nn;
            Bh[kk * LDB + nn] = g_wt_hi[widx];
            Bl[kk * LDB + nn] = g_wt_lo[widx];
        }
        __syncthreads();
        #pragma unroll
        for (int kk = 0; kk < 32; kk += 16) {
            wmma::fragment<wmma::matrix_a, 16, 16, 16, __nv_bfloat16, wmma::row_major> ah[2], al[2];
            wmma::fragment<wmma::matrix_b, 16, 16, 16, __nv_bfloat16, wmma::row_major> bh[2], bl[2];
            #pragma unroll
            for (int mi = 0; mi < 2; mi++) {
                int r = warp_m * 32 + mi * 16;
                wmma::load_matrix_sync(ah[mi], Ah + r * LDA + kk, LDA);
                wmma::load_matrix_sync(al[mi], Al + r * LDA + kk, LDA);
            }
            #pragma unroll
            for (int ni = 0; ni < 2; ni++) {
                int c = warp_n * 32 + ni * 16;
                wmma::load_matrix_sync(bh[ni], Bh + kk * LDB + c, LDB);
                wmma::load_matrix_sync(bl[ni], Bl + kk * LDB + c, LDB);
            }
            #pragma unroll
            for (int mi = 0; mi < 2; mi++)
                #pragma unroll
                for (int ni = 0; ni < 2; ni++) {
                    wmma::mma_sync(acc[mi][ni], ah[mi], bh[ni], acc[mi][ni]);
                    wmma::mma_sync(acc[mi][ni], ah[mi], bl[ni], acc[mi][ni]);
                    wmma::mma_sync(acc[mi][ni], al[mi], bh[ni], acc[mi][ni]);
                }
        }
        __syncthreads();
    }

    // stage accumulators to smem, then guarded coalesced store
    #pragma unroll
    for (int mi = 0; mi < 2; mi++)
        #pragma unroll
        for (int ni = 0; ni < 2; ni++)
            wmma::store_matrix_sync(ob + (warp_m * 32 + mi * 16) * 64 + warp_n * 32 + ni * 16,
                                    acc[mi][ni], 64, wmma::mem_row_major);
    __syncthreads();
    for (int i = tid; i < 128 * 64; i += 256) {
        int r = i >> 6, c = i & 63;
        int gr = row0 + r, gc = col0 + c;
        if (gr < M && gc < Nc) C[(size_t)gr * Nc + gc] = ob[i];
    }
}

// ---------------- BN stats over g_y (R2-proven pass) ------------------------
__global__ void k_stats(int M, int Nc) {
    __shared__ float ssum[512];
    __shared__ float ssq[512];
    int c = threadIdx.x, yy = threadIdx.y, by = blockDim.y;
    float s = 0.f, q = 0.f;
    for (int r = blockIdx.x * by + yy; r < M; r += gridDim.x * by) {
        float v = g_y[(size_t)r * Nc + c];
        s += v; q += v * v;
    }
    ssum[yy * Nc + c] = s;
    ssq[yy * Nc + c] = q;
    __syncthreads();
    if (yy == 0) {
        for (int j = 1; j < by; j++) { s += ssum[j * Nc + c]; q += ssq[j * Nc + c]; }
        atomicAdd(&g_sum[c], s);
        atomicAdd(&g_sq[c], q);
    }
}

__global__ void k_finalize(const float* __restrict__ gamma, const float* __restrict__ beta,
                           int M, int Nc) {
    int c = threadIdx.x;
    if (c < Nc) {
        float inv = 1.f / (float)M;
        float mean = g_sum[c] * inv;
        float var = g_sq[c] * inv - mean * mean;
        float r = rsqrtf(var + 1e-5f);
        float a = gamma[c] * r;
        g_scale[c] = a;
        g_shift[c] = beta[c] - mean * a;
    }
    g_sum[c] = 0.f;
    g_sq[c] = 0.f;
}

// ---------------- pooling & head ----------------
__global__ void k_bounds(const int* __restrict__ batch, int n, int nb) {
    int g = threadIdx.x;
    if (g > nb) return;
    int lo = 0, hi = n;
    while (lo < hi) {
        int mid = (lo + hi) >> 1;
        if (batch[mid] < g) lo = mid + 1; else hi = mid;
    }
    g_starts[g] = lo;
}

// reads g_x (pre-relu fc0 output); relu applied here (monotone => commutes with max)
__global__ void k_segmax() {
    __shared__ float sh[4][128];
    int g = blockIdx.x, c = threadIdx.x, s = threadIdx.y;
    int beg = g_starts[g], end = g_starts[g + 1];
    float m = -3.4e38f;
    for (int r = beg + s; r < end; r += 4)
        m = fmaxf(m, g_x[(size_t)r * 128 + c]);
    sh[s][c] = m;
    __syncthreads();
    if (s == 0) {
        m = fmaxf(fmaxf(sh[0][c], sh[1][c]), fmaxf(sh[2][c], sh[3][c]));
        g_pool[g * 128 + c] = fmaxf(m, 0.f);
    }
}

__global__ void k_head(const float* __restrict__ W1, const float* __restrict__ b1,
                       const float* __restrict__ W2, const float* __restrict__ b2,
                       const float* __restrict__ W3, const float* __restrict__ b3,
                       float* __restrict__ out) {
    __shared__ float xs[128];
    __shared__ float red[128];
    int g = blockIdx.x, c = threadIdx.x;
    xs[c] = g_pool[g * 128 + c];
    __syncthreads();

    float v = b1[c];
    #pragma unroll 8
    for (int k = 0; k < 128; k++) v = fmaf(xs[k], W1[k * 128 + c], v);
    v = fmaxf(v, 0.f);
    __syncthreads(); xs[c] = v; __syncthreads();

    v = b2[c];
    #pragma unroll 8
    for (int k = 0; k < 128; k++) v = fmaf(xs[k], W2[k * 128 + c], v);
    v = fmaxf(v, 0.f);
    __syncthreads(); xs[c] = v; __syncthreads();

    float v3 = b3[c];
    #pragma unroll 8
    for (int k = 0; k < 128; k++) v3 = fmaf(xs[k], W3[k * 128 + c], v3);

    red[c] = v3 * v3;
    __syncthreads();
    for (int off = 64; off > 0; off >>= 1) {
        if (c < off) red[c] += red[c + off];
        __syncthreads();
    }
    float nrm = fmaxf(sqrtf(red[0]), 1e-12f);
    out[g * 128 + c] = v3 / nrm;
}

// ---------------- host launch: kernel launches ONLY ----------------
extern "C" void kernel_launch(void* const* d_in, const int* in_sizes, int n_in,
                              void* d_out, int out_size) {
    const float* pos = (const float*)d_in[0];
    const int* ei = (const int*)d_in[1];
    const int* batch = (const int*)d_in[2];
    int n = in_sizes[0] / 3;
    int e = in_sizes[1] / 2;
    const int* src = ei;
    const int* dst = ei + e;
    float* out = (float*)d_out;

    const float *W[5], *bb[5], *gg[5], *be[5];
    for (int l = 0; l < 5; l++) {
        W[l]  = (const float*)d_in[3 + 4 * l];
        bb[l] = (const float*)d_in[4 + 4 * l];
        gg[l] = (const float*)d_in[5 + 4 * l];
        be[l] = (const float*)d_in[6 + 4 * l];
    }
    const float* fc0_W = (const float*)d_in[23];
    const float* fc0_b = (const float*)d_in[24];
    const float* fc1_W = (const float*)d_in[25];
    const float* fc1_b = (const float*)d_in[26];
    const float* fc2_W = (const float*)d_in[27];
    const float* fc2_b = (const float*)d_in[28];
    const float* fc3_W = (const float*)d_in[29];
    const float* fc3_b = (const float*)d_in[30];

    // ---- graph preprocessing ----
    k_zero<<<(n + 255) / 256, 256>>>(n);
    k_hist<<<(e + 255) / 256, 256>>>(dst, e);
    int nb = (n + 1023) / 1024;
    k_scan1<<<nb, 1024>>>(n);
    k_scan2<<<1, 256>>>(nb, n);
    k_place<<<(e + 255) / 256, 256>>>(src, dst, e);

    int aggBlocks = (n + 7) / 8;
    int rb128 = (n + 127) / 128;

    // ---- layer 1: 3 -> 16 ----
    k_agg<0><<<aggBlocks, 256>>>(pos, n, 3);
    k_gemm_s<3, 16><<<(n + 255) / 256, 256>>>(W[0], bb[0], n);
    k_finalize<<<1, 256>>>(gg[0], be[0], n, 16);

    // ---- layer 2: 16 -> 32 ----
    k_agg<1><<<aggBlocks, 256>>>(nullptr, n, 16);
    k_gemm_s<16, 32><<<(n + 255) / 256, 256>>>(W[1], bb[1], n);
    k_finalize<<<1, 256>>>(gg[1], be[1], n, 32);

    // ---- layer 3: 32 -> 64 (WMMA: Kpad=64, NTpad=64) ----
    k_agg<1><<<aggBlocks, 256>>>(nullptr, n, 32);
    k_wsplit<<<(64 * 64 + 255) / 256, 256>>>(W[2], bb[2], 32, 64, 64, 64);
    k_wmma<0><<<dim3(1, rb128), 256>>>(n, 32, 64, 64, 64);
    k_stats<<<1024, dim3(64, 8)>>>(n, 64);
    k_finalize<<<1, 256>>>(gg[2], be[2], n, 64);

    // ---- layer 4: 64 -> 94 (WMMA: Kpad=96, NTpad=128) ----
    k_agg<1><<<aggBlocks, 256>>>(nullptr, n, 64);
    k_wsplit<<<(96 * 128 + 255) / 256, 256>>>(W[3], bb[3], 64, 94, 128, 96);
    k_wmma<0><<<dim3(2, rb128), 256>>>(n, 64, 94, 96, 128);
    k_stats<<<1024, dim3(94, 5)>>>(n, 94);
    k_finalize<<<1, 256>>>(gg[3], be[3], n, 94);

    // ---- layer 5: 94 -> 256 (WMMA: Kpad=96, NTpad=256) ----
    k_agg<1><<<aggBlocks, 256>>>(nullptr, n, 94);
    k_wsplit<<<(96 * 256 + 255) / 256, 256>>>(W[4], bb[4], 94, 256, 256, 96);
    k_wmma<0><<<dim3(4, rb128), 256>>>(n, 94, 256, 96, 256);
    k_stats<<<1024, dim3(256, 2)>>>(n, 256);
    k_finalize<<<1, 256>>>(gg[4], be[4], n, 256);

    // ---- fc0: relu(bn(g_y)) @ W (256 -> 128), relu deferred (Kpad=288) ----
    k_wsplit<<<(288 * 128 + 255) / 256, 256>>>(fc0_W, fc0_b, 256, 128, 128, 288);
    k_wmma<1><<<dim3(2, rb128), 256>>>(n, 256, 128, 288, 128);

    // ---- segment max pool (+relu) + head MLP + normalize ----
    k_bounds<<<1, 65>>>(batch, n, 64);
    k_segmax<<<64, dim3(128, 4)>>>();
    k_head<<<64, 128>>>(fc1_W, fc1_b, fc2_W, fc2_b, fc3_W, fc3_b, out);
}